// round 1
// baseline (speedup 1.0000x reference)
#include <cuda_runtime.h>
#include <math.h>

// Problem constants
#define BB   2
#define SS   2048
#define HIDD 2048
#define HH   8
#define KKH  1
#define DD   256
#define HALF 128

// Scratch (device globals; no allocation allowed)
__device__ float g_q [BB * SS * HH * DD];   // (b, s, h, d)
__device__ float g_k [BB * SS * DD];        // (b, s, d)   KH = 1
__device__ float g_v [BB * SS * DD];
__device__ float g_oh[BB * SS * HH * DD];   // attention output heads (b, s, h*D)

// ---------------------------------------------------------------------------
// Generic NT GEMM: C[m,n] = alpha * sum_k A[m,k]*B[n,k]  (+ Add[n] if given)
// A: (M,K) row-major lda ; B: (N,K) row-major ldb ; C: row-major ldc
// Batched over blockIdx.z with z = zb*Hz + zh offsets.
// Block tile 128x128x8, 256 threads, 8x8 per thread.
// Requires M,N % 128 == 0, K % 8 == 0, rows 16B-aligned.
// ---------------------------------------------------------------------------
__global__ void gemm_nt(const float* __restrict__ A, const float* __restrict__ Bm,
                        const float* __restrict__ Add, float* __restrict__ C,
                        int M, int N, int K, int lda, int ldb, int ldc, float alpha,
                        int Hz,
                        long aSB, long aSH, long bSB, long bSH,
                        long cSB, long cSH, long addSB)
{
    int z  = blockIdx.z;
    int zb = z / Hz;
    int zh = z - zb * Hz;
    A  += zb * aSB + zh * aSH;
    Bm += zb * bSB + zh * bSH;
    C  += zb * cSB + zh * cSH;
    const float* add = Add ? (Add + zb * addSB) : nullptr;

    __shared__ __align__(16) float As[8][128];
    __shared__ __align__(16) float Bs[8][128];

    int tid = threadIdx.x;          // 0..255
    int tx  = tid & 15;             // n sub-tile
    int ty  = tid >> 4;             // m sub-tile
    int lr  = tid >> 1;             // 0..127 (row within tile for loads)
    int lk  = (tid & 1) * 4;        // 0 or 4

    const float* Ab = A  + (long)(blockIdx.y * 128) * lda;
    const float* Bb = Bm + (long)(blockIdx.x * 128) * ldb;

    float acc[8][8];
    #pragma unroll
    for (int i = 0; i < 8; i++)
        #pragma unroll
        for (int j = 0; j < 8; j++) acc[i][j] = 0.f;

    for (int k0 = 0; k0 < K; k0 += 8) {
        float4 a = *(const float4*)(Ab + (long)lr * lda + k0 + lk);
        float4 b = *(const float4*)(Bb + (long)lr * ldb + k0 + lk);
        As[lk + 0][lr] = a.x; As[lk + 1][lr] = a.y;
        As[lk + 2][lr] = a.z; As[lk + 3][lr] = a.w;
        Bs[lk + 0][lr] = b.x; Bs[lk + 1][lr] = b.y;
        Bs[lk + 2][lr] = b.z; Bs[lk + 3][lr] = b.w;
        __syncthreads();
        #pragma unroll
        for (int k = 0; k < 8; k++) {
            float4 a0 = *(const float4*)&As[k][ty * 8];
            float4 a1 = *(const float4*)&As[k][ty * 8 + 4];
            float4 b0 = *(const float4*)&Bs[k][tx * 8];
            float4 b1 = *(const float4*)&Bs[k][tx * 8 + 4];
            float ar[8] = {a0.x, a0.y, a0.z, a0.w, a1.x, a1.y, a1.z, a1.w};
            float br[8] = {b0.x, b0.y, b0.z, b0.w, b1.x, b1.y, b1.z, b1.w};
            #pragma unroll
            for (int i = 0; i < 8; i++)
                #pragma unroll
                for (int j = 0; j < 8; j++)
                    acc[i][j] = fmaf(ar[i], br[j], acc[i][j]);
        }
        __syncthreads();
    }

    int m0 = blockIdx.y * 128 + ty * 8;
    int n0 = blockIdx.x * 128 + tx * 8;
    float addv[8];
    #pragma unroll
    for (int j = 0; j < 8; j++) addv[j] = add ? add[n0 + j] : 0.f;
    #pragma unroll
    for (int i = 0; i < 8; i++) {
        float* Crow = C + (long)(m0 + i) * ldc + n0;
        #pragma unroll
        for (int j = 0; j < 8; j++)
            Crow[j] = acc[i][j] * alpha + addv[j];
    }
}

// ---------------------------------------------------------------------------
// Generic NN GEMM: C[m,n] = sum_k A[m,k]*B[k,n]
// A: (M,K) row-major lda ; B: (K,N) row-major ldb ; C: row-major ldc
// Same tiling. Batched over blockIdx.z.
// ---------------------------------------------------------------------------
__global__ void gemm_nn(const float* __restrict__ A, const float* __restrict__ Bm,
                        float* __restrict__ C,
                        int M, int N, int K, int lda, int ldb, int ldc,
                        int Hz,
                        long aSB, long aSH, long bSB, long bSH,
                        long cSB, long cSH)
{
    int z  = blockIdx.z;
    int zb = z / Hz;
    int zh = z - zb * Hz;
    A  += zb * aSB + zh * aSH;
    Bm += zb * bSB + zh * bSH;
    C  += zb * cSB + zh * cSH;

    __shared__ __align__(16) float As[8][128];
    __shared__ __align__(16) float Bs[8][128];

    int tid = threadIdx.x;
    int tx  = tid & 15;
    int ty  = tid >> 4;
    int lr  = tid >> 1;             // A: row within tile
    int lk  = (tid & 1) * 4;        // A: k offset
    int bk  = tid >> 5;             // B: k row 0..7
    int bn  = (tid & 31) * 4;       // B: n offset 0..124

    const float* Ab = A + (long)(blockIdx.y * 128) * lda;
    const float* Bb = Bm + blockIdx.x * 128;

    float acc[8][8];
    #pragma unroll
    for (int i = 0; i < 8; i++)
        #pragma unroll
        for (int j = 0; j < 8; j++) acc[i][j] = 0.f;

    for (int k0 = 0; k0 < K; k0 += 8) {
        float4 a = *(const float4*)(Ab + (long)lr * lda + k0 + lk);
        float4 b = *(const float4*)(Bb + (long)(k0 + bk) * ldb + bn);
        As[lk + 0][lr] = a.x; As[lk + 1][lr] = a.y;
        As[lk + 2][lr] = a.z; As[lk + 3][lr] = a.w;
        *(float4*)&Bs[bk][bn] = b;
        __syncthreads();
        #pragma unroll
        for (int k = 0; k < 8; k++) {
            float4 a0 = *(const float4*)&As[k][ty * 8];
            float4 a1 = *(const float4*)&As[k][ty * 8 + 4];
            float4 b0 = *(const float4*)&Bs[k][tx * 8];
            float4 b1 = *(const float4*)&Bs[k][tx * 8 + 4];
            float ar[8] = {a0.x, a0.y, a0.z, a0.w, a1.x, a1.y, a1.z, a1.w};
            float br[8] = {b0.x, b0.y, b0.z, b0.w, b1.x, b1.y, b1.z, b1.w};
            #pragma unroll
            for (int i = 0; i < 8; i++)
                #pragma unroll
                for (int j = 0; j < 8; j++)
                    acc[i][j] = fmaf(ar[i], br[j], acc[i][j]);
        }
        __syncthreads();
    }

    int m0 = blockIdx.y * 128 + ty * 8;
    int n0 = blockIdx.x * 128 + tx * 8;
    #pragma unroll
    for (int i = 0; i < 8; i++) {
        float* Crow = C + (long)(m0 + i) * ldc + n0;
        #pragma unroll
        for (int j = 0; j < 8; j++)
            Crow[j] = acc[i][j];
    }
}

// ---------------------------------------------------------------------------
// RoPE: in-place on g_q (B*S*H rows) and g_k (B*S rows). 128 threads per row.
// ---------------------------------------------------------------------------
__global__ void rope_kernel(float* __restrict__ q, float* __restrict__ k,
                            const int* __restrict__ pos)
{
    int bid = blockIdx.x;
    const int NQ = BB * SS * HH;
    float* ptr;
    int b, s;
    if (bid < NQ) {
        int h = bid % HH;
        s = (bid / HH) % SS;
        b = bid / (HH * SS);
        ptr = q + (((long)(b * SS + s)) * HH + h) * DD;
    } else {
        int idx = bid - NQ;
        s = idx % SS;
        b = idx / SS;
        ptr = k + ((long)(b * SS + s)) * DD;
    }
    int i = threadIdx.x;                       // 0..127
    float p = (float)pos[b * SS + s];
    float inv = powf(10000.0f, -((float)(2 * i)) / (float)DD);
    float fr = p * inv;
    float c, sn;
    sincosf(fr, &sn, &c);
    float x1 = ptr[i];
    float x2 = ptr[i + HALF];
    ptr[i]        = c * x1 - sn * x2;
    ptr[i + HALF] = sn * x1 + c * x2;
}

// ---------------------------------------------------------------------------
// Row softmax over last dim (S=2048). One block (256 thr) per row.
// ---------------------------------------------------------------------------
__global__ void softmax_kernel(float* __restrict__ attn)
{
    long row = blockIdx.x;                     // B*H*S rows
    float* p = attn + row * (long)SS;
    int t = threadIdx.x;
    float v[8];
    #pragma unroll
    for (int i = 0; i < 8; i++) v[i] = p[t + i * 256];

    float m = -3.4e38f;
    #pragma unroll
    for (int i = 0; i < 8; i++) m = fmaxf(m, v[i]);
    #pragma unroll
    for (int o = 16; o > 0; o >>= 1) m = fmaxf(m, __shfl_xor_sync(0xffffffffu, m, o));
    __shared__ float smax[8];
    __shared__ float ssum[8];
    if ((t & 31) == 0) smax[t >> 5] = m;
    __syncthreads();
    float bm = smax[0];
    #pragma unroll
    for (int i = 1; i < 8; i++) bm = fmaxf(bm, smax[i]);

    float sum = 0.f;
    #pragma unroll
    for (int i = 0; i < 8; i++) { v[i] = expf(v[i] - bm); sum += v[i]; }
    #pragma unroll
    for (int o = 16; o > 0; o >>= 1) sum += __shfl_xor_sync(0xffffffffu, sum, o);
    if ((t & 31) == 0) ssum[t >> 5] = sum;
    __syncthreads();
    float tot = 0.f;
    #pragma unroll
    for (int i = 0; i < 8; i++) tot += ssum[i];
    float invs = 1.0f / tot;
    #pragma unroll
    for (int i = 0; i < 8; i++) p[t + i * 256] = v[i] * invs;
}

// ---------------------------------------------------------------------------
extern "C" void kernel_launch(void* const* d_in, const int* in_sizes, int n_in,
                              void* d_out, int out_size)
{
    const float* hs   = (const float*)d_in[0];
    const float* mask = (const float*)d_in[1];
    const int*   pos  = (const int*)  d_in[2];
    const float* Wq   = (const float*)d_in[3];
    const float* bq   = (const float*)d_in[4];
    const float* Wk   = (const float*)d_in[5];
    const float* bk   = (const float*)d_in[6];
    const float* Wv   = (const float*)d_in[7];
    const float* bv   = (const float*)d_in[8];
    const float* Wo   = (const float*)d_in[9];
    const float* bo   = (const float*)d_in[10];

    float* out  = (float*)d_out;                               // (B,S,HID)
    float* attn = out + (size_t)BB * SS * HIDD;                // (B,H,S,S)

    float *qp, *kp, *vp, *ohp;
    cudaGetSymbolAddress((void**)&qp,  g_q);
    cudaGetSymbolAddress((void**)&kp,  g_k);
    cudaGetSymbolAddress((void**)&vp,  g_v);
    cudaGetSymbolAddress((void**)&ohp, g_oh);

    dim3 blk(256);
    const int M = BB * SS;          // 4096 token rows

    // Q = hs @ Wq^T + bq
    gemm_nt<<<dim3(HIDD / 128, M / 128, 1), blk>>>(
        hs, Wq, bq, qp, M, HIDD, HIDD, HIDD, HIDD, HIDD, 1.0f,
        1, 0, 0, 0, 0, 0, 0, 0);
    // K = hs @ Wk^T + bk
    gemm_nt<<<dim3(DD / 128, M / 128, 1), blk>>>(
        hs, Wk, bk, kp, M, DD, HIDD, HIDD, HIDD, DD, 1.0f,
        1, 0, 0, 0, 0, 0, 0, 0);
    // V = hs @ Wv^T + bv
    gemm_nt<<<dim3(DD / 128, M / 128, 1), blk>>>(
        hs, Wv, bv, vp, M, DD, HIDD, HIDD, HIDD, DD, 1.0f,
        1, 0, 0, 0, 0, 0, 0, 0);

    // RoPE on q and k
    rope_kernel<<<BB * SS * HH + BB * SS, 128>>>(qp, kp, pos);

    // scores = (q @ k^T) * D^-0.5 + mask  -> attn buffer (B,H,S,S)
    gemm_nt<<<dim3(SS / 128, SS / 128, BB * HH), blk>>>(
        qp, kp, mask, attn, SS, SS, DD, HIDD, DD, SS, 0.0625f,
        HH,
        (long)SS * HIDD, (long)DD,           // A: q  (b stride, h stride)
        (long)SS * DD,   0,                  // B: k
        (long)HH * SS * SS, (long)SS * SS,   // C: attn
        (long)SS);                           // mask b stride

    // softmax rows
    softmax_kernel<<<BB * HH * SS, 256>>>(attn);

    // oh = attn @ v   (NN)
    gemm_nn<<<dim3(DD / 128, SS / 128, BB * HH), blk>>>(
        attn, vp, ohp, SS, DD, SS, SS, DD, HIDD,
        HH,
        (long)HH * SS * SS, (long)SS * SS,   // A: attn
        (long)SS * DD, 0,                    // B: v
        (long)SS * HIDD, (long)DD);          // C: oh

    // out = oh @ Wo^T + bo
    gemm_nt<<<dim3(HIDD / 128, M / 128, 1), blk>>>(
        ohp, Wo, bo, out, M, HIDD, HIDD, HIDD, HIDD, HIDD, 1.0f,
        1, 0, 0, 0, 0, 0, 0, 0);
}

// round 2
// speedup vs baseline: 1.9578x; 1.9578x over previous
#include <cuda_runtime.h>
#include <math.h>
#include <stdint.h>

// Problem constants
#define BB   2
#define SS   2048
#define HIDD 2048
#define HH   8
#define KKH  1
#define DD   256
#define HALF 128

// Scratch (device globals; no allocation allowed)
__device__ float g_q [BB * SS * HH * DD];   // (b, s, h, d)
__device__ float g_k [BB * SS * DD];        // (b, s, d)   KH = 1
__device__ float g_v [BB * SS * DD];
__device__ float g_oh[BB * SS * HH * DD];   // attention output heads (b, s, h*D)

// ---------------------------------------------------------------------------
// Helpers
// ---------------------------------------------------------------------------
__device__ __forceinline__ uint32_t f2tf(float x) {
    uint32_t r;
    asm("cvt.rna.tf32.f32 %0, %1;" : "=r"(r) : "f"(x));
    return r;
}

__device__ __forceinline__ void mma_tf32(float c[4],
                                         uint32_t a0, uint32_t a1, uint32_t a2, uint32_t a3,
                                         uint32_t b0, uint32_t b1) {
    asm volatile(
        "mma.sync.aligned.m16n8k8.row.col.f32.tf32.tf32.f32 "
        "{%0,%1,%2,%3}, {%4,%5,%6,%7}, {%8,%9}, {%0,%1,%2,%3};"
        : "+f"(c[0]), "+f"(c[1]), "+f"(c[2]), "+f"(c[3])
        : "r"(a0), "r"(a1), "r"(a2), "r"(a3), "r"(b0), "r"(b1));
}

// ---------------------------------------------------------------------------
// Tensor-core tf32 GEMM.
//   BNT = true :  C = alpha * A(M,K) @ B(N,K)^T + add[n]     (both k-contig)
//   BNT = false:  C = alpha * A(M,K) @ B(K,N)   + add[n]     (B n-contig)
// Block tile 128x128x16, 256 threads (8 warps, 2x4), warp tile 64x32.
// Requires M,N % 128 == 0, K % 16 == 0, 16B-aligned rows.
// Batched over blockIdx.z with z = zb*Hz + zh.
// ---------------------------------------------------------------------------
template <bool BNT>
__global__ void __launch_bounds__(256, 2)
tc_gemm(const float* __restrict__ A, const float* __restrict__ B,
        const float* __restrict__ Add, float* __restrict__ C,
        int M, int N, int K, int lda, int ldb, int ldc, float alpha,
        int Hz,
        long aSB, long aSH, long bSB, long bSH,
        long cSB, long cSH, long addSB)
{
    int z  = blockIdx.z;
    int zb = z / Hz;
    int zh = z - zb * Hz;
    A += zb * aSB + zh * aSH;
    B += zb * bSB + zh * bSH;
    C += zb * cSB + zh * cSH;
    const float* add = Add ? (Add + zb * addSB) : nullptr;

    // k-major tiles, stride 136 -> fragment loads conflict-free (bank = 8k+mn)
    __shared__ __align__(16) uint32_t As[16][136];
    __shared__ __align__(16) uint32_t Bs[16][136];

    int tid  = threadIdx.x;
    int warp = tid >> 5;
    int lane = tid & 31;
    int gid  = lane >> 2;       // 0..7
    int tid4 = lane & 3;        // 0..3
    int wm0  = (warp >> 2) * 64;   // warp m origin in tile
    int wn0  = (warp & 3) * 32;    // warp n origin in tile

    const float* Ab = A + (long)(blockIdx.y * 128) * lda;
    const float* Bb = BNT ? (B + (long)(blockIdx.x * 128) * ldb)
                          : (B + blockIdx.x * 128);

    // load mappings
    int am  = tid & 127;          // A row in tile
    int akq = (tid >> 7) * 8;     // A k offset (0 or 8)
    int nn0 = (tid & 31) * 4;     // B(NN) n offset
    int nbk = tid >> 5;           // B(NN) k row (0..7; also +8)

    float c[4][4][4];
    #pragma unroll
    for (int im = 0; im < 4; im++)
        #pragma unroll
        for (int in = 0; in < 4; in++)
            #pragma unroll
            for (int r = 0; r < 4; r++) c[im][in][r] = 0.f;

    for (int k0 = 0; k0 < K; k0 += 16) {
        // ---- A tile: rows m, k-contig ----
        #pragma unroll
        for (int q = 0; q < 2; q++) {
            float4 a = *(const float4*)(Ab + (long)am * lda + k0 + akq + 4 * q);
            As[akq + 4 * q + 0][am] = f2tf(a.x);
            As[akq + 4 * q + 1][am] = f2tf(a.y);
            As[akq + 4 * q + 2][am] = f2tf(a.z);
            As[akq + 4 * q + 3][am] = f2tf(a.w);
        }
        // ---- B tile ----
        if (BNT) {
            #pragma unroll
            for (int q = 0; q < 2; q++) {
                float4 b = *(const float4*)(Bb + (long)am * ldb + k0 + akq + 4 * q);
                Bs[akq + 4 * q + 0][am] = f2tf(b.x);
                Bs[akq + 4 * q + 1][am] = f2tf(b.y);
                Bs[akq + 4 * q + 2][am] = f2tf(b.z);
                Bs[akq + 4 * q + 3][am] = f2tf(b.w);
            }
        } else {
            #pragma unroll
            for (int r = 0; r < 2; r++) {
                int kr = nbk + 8 * r;
                float4 b = *(const float4*)(Bb + (long)(k0 + kr) * ldb + nn0);
                uint4 bb;
                bb.x = f2tf(b.x); bb.y = f2tf(b.y);
                bb.z = f2tf(b.z); bb.w = f2tf(b.w);
                *(uint4*)&Bs[kr][nn0] = bb;
            }
        }
        __syncthreads();

        #pragma unroll
        for (int kk = 0; kk < 16; kk += 8) {
            uint32_t af[4][4], bf[4][2];
            #pragma unroll
            for (int im = 0; im < 4; im++) {
                int m = wm0 + 16 * im + gid;
                af[im][0] = As[kk + tid4][m];
                af[im][1] = As[kk + tid4][m + 8];
                af[im][2] = As[kk + tid4 + 4][m];
                af[im][3] = As[kk + tid4 + 4][m + 8];
            }
            #pragma unroll
            for (int in = 0; in < 4; in++) {
                int n = wn0 + 8 * in + gid;
                bf[in][0] = Bs[kk + tid4][n];
                bf[in][1] = Bs[kk + tid4 + 4][n];
            }
            #pragma unroll
            for (int im = 0; im < 4; im++)
                #pragma unroll
                for (int in = 0; in < 4; in++)
                    mma_tf32(c[im][in], af[im][0], af[im][1], af[im][2], af[im][3],
                             bf[in][0], bf[in][1]);
        }
        __syncthreads();
    }

    // ---- epilogue ----
    int m0 = blockIdx.y * 128 + wm0;
    int n0 = blockIdx.x * 128 + wn0;
    #pragma unroll
    for (int im = 0; im < 4; im++) {
        #pragma unroll
        for (int in = 0; in < 4; in++) {
            int r0 = m0 + 16 * im + gid;
            int cc = n0 + 8 * in + 2 * tid4;
            float a0 = add ? add[cc] : 0.f;
            float a1 = add ? add[cc + 1] : 0.f;
            float2 v0 = make_float2(c[im][in][0] * alpha + a0,
                                    c[im][in][1] * alpha + a1);
            float2 v1 = make_float2(c[im][in][2] * alpha + a0,
                                    c[im][in][3] * alpha + a1);
            *(float2*)&C[(long)r0 * ldc + cc]       = v0;
            *(float2*)&C[(long)(r0 + 8) * ldc + cc] = v1;
        }
    }
}

// ---------------------------------------------------------------------------
// RoPE: in-place on g_q (B*S*H rows) and g_k (B*S rows). 128 threads per row.
// ---------------------------------------------------------------------------
__global__ void rope_kernel(float* __restrict__ q, float* __restrict__ k,
                            const int* __restrict__ pos)
{
    int bid = blockIdx.x;
    const int NQ = BB * SS * HH;
    float* ptr;
    int b, s;
    if (bid < NQ) {
        int h = bid % HH;
        s = (bid / HH) % SS;
        b = bid / (HH * SS);
        ptr = q + (((long)(b * SS + s)) * HH + h) * DD;
    } else {
        int idx = bid - NQ;
        s = idx % SS;
        b = idx / SS;
        ptr = k + ((long)(b * SS + s)) * DD;
    }
    int i = threadIdx.x;                       // 0..127
    float p = (float)pos[b * SS + s];
    float inv = powf(10000.0f, -((float)(2 * i)) / (float)DD);
    float fr = p * inv;
    float c, sn;
    sincosf(fr, &sn, &c);
    float x1 = ptr[i];
    float x2 = ptr[i + HALF];
    ptr[i]        = c * x1 - sn * x2;
    ptr[i + HALF] = sn * x1 + c * x2;
}

// ---------------------------------------------------------------------------
// Row softmax over last dim (S=2048). One block (256 thr) per row.
// ---------------------------------------------------------------------------
__global__ void softmax_kernel(float* __restrict__ attn)
{
    long row = blockIdx.x;                     // B*H*S rows
    float* p = attn + row * (long)SS;
    int t = threadIdx.x;
    float v[8];
    #pragma unroll
    for (int i = 0; i < 8; i++) v[i] = p[t + i * 256];

    float m = -3.4e38f;
    #pragma unroll
    for (int i = 0; i < 8; i++) m = fmaxf(m, v[i]);
    #pragma unroll
    for (int o = 16; o > 0; o >>= 1) m = fmaxf(m, __shfl_xor_sync(0xffffffffu, m, o));
    __shared__ float smax[8];
    __shared__ float ssum[8];
    if ((t & 31) == 0) smax[t >> 5] = m;
    __syncthreads();
    float bm = smax[0];
    #pragma unroll
    for (int i = 1; i < 8; i++) bm = fmaxf(bm, smax[i]);

    float sum = 0.f;
    #pragma unroll
    for (int i = 0; i < 8; i++) { v[i] = expf(v[i] - bm); sum += v[i]; }
    #pragma unroll
    for (int o = 16; o > 0; o >>= 1) sum += __shfl_xor_sync(0xffffffffu, sum, o);
    if ((t & 31) == 0) ssum[t >> 5] = sum;
    __syncthreads();
    float tot = 0.f;
    #pragma unroll
    for (int i = 0; i < 8; i++) tot += ssum[i];
    float invs = 1.0f / tot;
    #pragma unroll
    for (int i = 0; i < 8; i++) p[t + i * 256] = v[i] * invs;
}

// ---------------------------------------------------------------------------
extern "C" void kernel_launch(void* const* d_in, const int* in_sizes, int n_in,
                              void* d_out, int out_size)
{
    const float* hs   = (const float*)d_in[0];
    const float* mask = (const float*)d_in[1];
    const int*   pos  = (const int*)  d_in[2];
    const float* Wq   = (const float*)d_in[3];
    const float* bq   = (const float*)d_in[4];
    const float* Wk   = (const float*)d_in[5];
    const float* bk   = (const float*)d_in[6];
    const float* Wv   = (const float*)d_in[7];
    const float* bv   = (const float*)d_in[8];
    const float* Wo   = (const float*)d_in[9];
    const float* bo   = (const float*)d_in[10];

    float* out  = (float*)d_out;                               // (B,S,HID)
    float* attn = out + (size_t)BB * SS * HIDD;                // (B,H,S,S)

    float *qp, *kp, *vp, *ohp;
    cudaGetSymbolAddress((void**)&qp,  g_q);
    cudaGetSymbolAddress((void**)&kp,  g_k);
    cudaGetSymbolAddress((void**)&vp,  g_v);
    cudaGetSymbolAddress((void**)&ohp, g_oh);

    dim3 blk(256);
    const int M = BB * SS;          // 4096 token rows

    // Q = hs @ Wq^T + bq
    tc_gemm<true><<<dim3(HIDD / 128, M / 128, 1), blk>>>(
        hs, Wq, bq, qp, M, HIDD, HIDD, HIDD, HIDD, HIDD, 1.0f,
        1, 0, 0, 0, 0, 0, 0, 0);
    // K = hs @ Wk^T + bk
    tc_gemm<true><<<dim3(DD / 128, M / 128, 1), blk>>>(
        hs, Wk, bk, kp, M, DD, HIDD, HIDD, HIDD, DD, 1.0f,
        1, 0, 0, 0, 0, 0, 0, 0);
    // V = hs @ Wv^T + bv
    tc_gemm<true><<<dim3(DD / 128, M / 128, 1), blk>>>(
        hs, Wv, bv, vp, M, DD, HIDD, HIDD, HIDD, DD, 1.0f,
        1, 0, 0, 0, 0, 0, 0, 0);

    // RoPE on q and k
    rope_kernel<<<BB * SS * HH + BB * SS, 128>>>(qp, kp, pos);

    // scores = (q @ k^T) * D^-0.5 + mask  -> attn buffer (B,H,S,S)
    tc_gemm<true><<<dim3(SS / 128, SS / 128, BB * HH), blk>>>(
        qp, kp, mask, attn, SS, SS, DD, HIDD, DD, SS, 0.0625f,
        HH,
        (long)SS * HIDD, (long)DD,           // A: q  (b stride, h stride)
        (long)SS * DD,   0,                  // B: k
        (long)HH * SS * SS, (long)SS * SS,   // C: attn
        (long)SS);                           // mask b stride

    // softmax rows
    softmax_kernel<<<BB * HH * SS, 256>>>(attn);

    // oh = attn @ v   (NN)
    tc_gemm<false><<<dim3(DD / 128, SS / 128, BB * HH), blk>>>(
        attn, vp, nullptr, ohp, SS, DD, SS, SS, DD, HIDD, 1.0f,
        HH,
        (long)HH * SS * SS, (long)SS * SS,   // A: attn
        (long)SS * DD, 0,                    // B: v
        (long)SS * HIDD, (long)DD,           // C: oh
        0);

    // out = oh @ Wo^T + bo
    tc_gemm<true><<<dim3(HIDD / 128, M / 128, 1), blk>>>(
        ohp, Wo, bo, out, M, HIDD, HIDD, HIDD, HIDD, HIDD, 1.0f,
        1, 0, 0, 0, 0, 0, 0, 0);
}

// round 5
// speedup vs baseline: 5.2911x; 2.7025x over previous
#include <cuda_runtime.h>
#include <cuda_fp16.h>
#include <math.h>
#include <stdint.h>

// Problem constants
#define BB   2
#define SS   2048
#define HIDD 2048
#define HH   8
#define DD   256
#define HALF 128

// fp16 scratch (device globals; no allocation allowed)
__device__ __half g_hs16[BB * SS * HIDD];
__device__ __half g_wq16[HIDD * HIDD];
__device__ __half g_wk16[DD * HIDD];
__device__ __half g_wv16[DD * HIDD];
__device__ __half g_wo16[HIDD * HIDD];
__device__ __half g_q16 [BB * SS * HH * DD];    // (b,s,h,d)
__device__ __half g_k16 [BB * SS * DD];         // (b,s,d)
__device__ __half g_vt16[BB * DD * SS];         // (b,d,s) = V^T
__device__ __half g_p16 [(size_t)BB * HH * SS * SS];  // fp16 attn probs
__device__ __half g_oh16[BB * SS * HH * DD];    // (b,s,h*D)

// ---------------------------------------------------------------------------
__device__ __forceinline__ uint32_t smem_u32(const void* p) {
    uint32_t a;
    asm("{ .reg .u64 t; cvta.to.shared.u64 t, %1; cvt.u32.u64 %0, t; }" : "=r"(a) : "l"(p));
    return a;
}
__device__ __forceinline__ void cpa16(uint32_t dst, const void* src) {
    asm volatile("cp.async.cg.shared.global [%0], [%1], 16;" :: "r"(dst), "l"(src) : "memory");
}
#define CP_COMMIT() asm volatile("cp.async.commit_group;" ::: "memory")

__device__ __forceinline__ void ldsm4(uint32_t r[4], uint32_t addr) {
    asm volatile("ldmatrix.sync.aligned.m8n8.x4.shared.b16 {%0,%1,%2,%3}, [%4];"
                 : "=r"(r[0]), "=r"(r[1]), "=r"(r[2]), "=r"(r[3]) : "r"(addr));
}
__device__ __forceinline__ void mma_f16(float c[4], const uint32_t a[4], const uint32_t* b) {
    asm volatile(
        "mma.sync.aligned.m16n8k16.row.col.f32.f16.f16.f32 "
        "{%0,%1,%2,%3}, {%4,%5,%6,%7}, {%8,%9}, {%0,%1,%2,%3};"
        : "+f"(c[0]), "+f"(c[1]), "+f"(c[2]), "+f"(c[3])
        : "r"(a[0]), "r"(a[1]), "r"(a[2]), "r"(a[3]), "r"(b[0]), "r"(b[1]));
}

// ---------------------------------------------------------------------------
// fp16 NT GEMM: C = alpha * A(M,K) @ B(N,K)^T + bias
//   A, B fp16 k-contiguous. CT = float or __half output.
//   AMODE: 0 = no bias, 1 = column bias Add[n] (fp32), 2 = row bias Add[m]
// Block 128x128x32, 256 threads (8 warps, 2x4), warp tile 64x32.
// Double-buffered smem via cp.async; ldmatrix fragment loads.
// Requires M,N % 128 == 0, K % 32 == 0.
// ---------------------------------------------------------------------------
#define APITCH 80   // bytes per 32-half row (64B data + 16B pad)

template <typename CT, int AMODE>
__global__ void __launch_bounds__(256, 2)
h_gemm(const __half* __restrict__ A, const __half* __restrict__ B,
       const float* __restrict__ Add, CT* __restrict__ C,
       int K, int lda, int ldb, int ldc, float alpha, int Hz,
       long aSB, long aSH, long bSB, long bSH, long cSB, long cSH, long addSB)
{
    __shared__ __align__(16) char smem[4 * 128 * APITCH + 512];
    const uint32_t sb = smem_u32(smem);
    const uint32_t AsS[2] = {sb,                  sb + 128 * APITCH};
    const uint32_t BsS[2] = {sb + 2*128*APITCH,   sb + 3*128*APITCH};
    float* add_s = (float*)(smem + 4 * 128 * APITCH);

    const int tid  = threadIdx.x;
    const int warp = tid >> 5, lane = tid & 31;
    const int gid  = lane >> 2, tid4 = lane & 3;
    const int wm0  = (warp >> 2) * 64;
    const int wn0  = (warp & 3) * 32;

    const int z  = blockIdx.z;
    const int zb = z / Hz;
    const int zh = z - zb * Hz;
    A += zb * aSB + zh * aSH;
    B += zb * bSB + zh * bSH;
    C += zb * cSB + zh * cSH;

    if (AMODE == 1 && tid < 128)
        add_s[tid] = Add[zb * addSB + blockIdx.x * 128 + tid];

    const __half* Ab = A + (long)(blockIdx.y * 128) * lda;
    const __half* Bb = B + (long)(blockIdx.x * 128) * ldb;

    // cp.async mapping: 2 threads per row, 2x16B each
    const int lrow = tid >> 1;
    const int lch  = (tid & 1) * 16;   // halves offset (0 or 16)

    const int nIt = K / 32;

    // fragment smem addresses (constant across iters except buffer base)
    const uint32_t aoff = (uint32_t)((wm0 + (lane & 15)) * APITCH + (lane >> 4) * 16);
    const uint32_t boff = (uint32_t)((wn0 + (lane & 7) + ((lane >> 4) & 1) * 8) * APITCH
                                     + ((lane >> 3) & 1) * 16);

    float c[4][4][4];
    #pragma unroll
    for (int im = 0; im < 4; im++)
        #pragma unroll
        for (int in = 0; in < 4; in++)
            #pragma unroll
            for (int r = 0; r < 4; r++) c[im][in][r] = 0.f;

    // prologue: fetch tiles 0, 1
    #pragma unroll
    for (int p = 0; p < 2; p++) {
        const int k0 = p * 32;
        const uint32_t da = AsS[p] + lrow * APITCH + lch * 2;
        const uint32_t db = BsS[p] + lrow * APITCH + lch * 2;
        cpa16(da,      Ab + (long)lrow * lda + k0 + lch);
        cpa16(da + 16, Ab + (long)lrow * lda + k0 + lch + 8);
        cpa16(db,      Bb + (long)lrow * ldb + k0 + lch);
        cpa16(db + 16, Bb + (long)lrow * ldb + k0 + lch + 8);
        CP_COMMIT();
    }

    for (int it = 0; it < nIt; ++it) {
        const int buf = it & 1;
        if (it + 1 < nIt) asm volatile("cp.async.wait_group 1;" ::: "memory");
        else              asm volatile("cp.async.wait_group 0;" ::: "memory");
        __syncthreads();

        // compute on buf
        #pragma unroll
        for (int kk = 0; kk < 32; kk += 16) {
            uint32_t af[4][4], bf[2][4];
            #pragma unroll
            for (int im = 0; im < 4; im++)
                ldsm4(af[im], AsS[buf] + aoff + im * (16 * APITCH) + kk * 2);
            #pragma unroll
            for (int ng = 0; ng < 2; ng++)
                ldsm4(bf[ng], BsS[buf] + boff + ng * (16 * APITCH) + kk * 2);
            #pragma unroll
            for (int im = 0; im < 4; im++)
                #pragma unroll
                for (int in = 0; in < 4; in++)
                    mma_f16(c[im][in], af[im], &bf[in >> 1][(in & 1) * 2]);
        }
        __syncthreads();

        // fetch tile it+2 into buf
        if (it + 2 < nIt) {
            const int k0 = (it + 2) * 32;
            const uint32_t da = AsS[buf] + lrow * APITCH + lch * 2;
            const uint32_t db = BsS[buf] + lrow * APITCH + lch * 2;
            cpa16(da,      Ab + (long)lrow * lda + k0 + lch);
            cpa16(da + 16, Ab + (long)lrow * lda + k0 + lch + 8);
            cpa16(db,      Bb + (long)lrow * ldb + k0 + lch);
            cpa16(db + 16, Bb + (long)lrow * ldb + k0 + lch + 8);
            CP_COMMIT();
        }
    }

    // epilogue
    const int m0 = blockIdx.y * 128 + wm0;
    const int n0 = blockIdx.x * 128 + wn0;
    float rb0 = 0.f, rb1 = 0.f;
    if (AMODE == 2) {
        rb0 = Add[zb * addSB + m0 + gid];       // rows +0..  (per im below adjust)
    }
    #pragma unroll
    for (int im = 0; im < 4; im++) {
        const long r0 = m0 + im * 16 + gid;
        if (AMODE == 2) {
            rb0 = Add[zb * addSB + r0];
            rb1 = Add[zb * addSB + r0 + 8];
        }
        #pragma unroll
        for (int in = 0; in < 4; in++) {
            const int cc = n0 + in * 8 + tid4 * 2;
            float b0 = 0.f, b1 = 0.f;
            if (AMODE == 1) { b0 = add_s[wn0 + in * 8 + tid4 * 2]; b1 = add_s[wn0 + in * 8 + tid4 * 2 + 1]; }
            float v0 = c[im][in][0] * alpha + (AMODE == 2 ? rb0 : b0);
            float v1 = c[im][in][1] * alpha + (AMODE == 2 ? rb0 : b1);
            float v2 = c[im][in][2] * alpha + (AMODE == 2 ? rb1 : b0);
            float v3 = c[im][in][3] * alpha + (AMODE == 2 ? rb1 : b1);
            if (sizeof(CT) == 4) {
                float* Cp = (float*)C;
                *(float2*)&Cp[r0 * ldc + cc]       = make_float2(v0, v1);
                *(float2*)&Cp[(r0 + 8) * ldc + cc] = make_float2(v2, v3);
            } else {
                __half* Cp = (__half*)C;
                *(__half2*)&Cp[r0 * ldc + cc]       = __floats2half2_rn(v0, v1);
                *(__half2*)&Cp[(r0 + 8) * ldc + cc] = __floats2half2_rn(v2, v3);
            }
        }
    }
}

// ---------------------------------------------------------------------------
// fp32 -> fp16 convert (n % 1024 == 0)
// ---------------------------------------------------------------------------
__global__ void f2h_kernel(const float* __restrict__ src, __half* __restrict__ dst, int n)
{
    int i = (blockIdx.x * 256 + threadIdx.x) * 4;
    if (i < n) {
        float4 v = *(const float4*)(src + i);
        __half2 h0 = __floats2half2_rn(v.x, v.y);
        __half2 h1 = __floats2half2_rn(v.z, v.w);
        *(__half2*)(dst + i)     = h0;
        *(__half2*)(dst + i + 2) = h1;
    }
}

// ---------------------------------------------------------------------------
// RoPE in fp16: in-place on g_q16 (B*S*H rows) and g_k16 (B*S rows).
// ---------------------------------------------------------------------------
__global__ void rope_kernel(__half* __restrict__ q, __half* __restrict__ k,
                            const int* __restrict__ pos)
{
    int bid = blockIdx.x;
    const int NQ = BB * SS * HH;
    __half* ptr;
    int b, s;
    if (bid < NQ) {
        int h = bid % HH;
        s = (bid / HH) % SS;
        b = bid / (HH * SS);
        ptr = q + (((long)(b * SS + s)) * HH + h) * DD;
    } else {
        int idx = bid - NQ;
        s = idx % SS;
        b = idx / SS;
        ptr = k + ((long)(b * SS + s)) * DD;
    }
    int i = threadIdx.x;                       // 0..127
    float p = (float)pos[b * SS + s];
    float inv = powf(10000.0f, -((float)(2 * i)) / (float)DD);
    float fr = p * inv;
    float cs, sn;
    sincosf(fr, &sn, &cs);
    float x1 = __half2float(ptr[i]);
    float x2 = __half2float(ptr[i + HALF]);
    ptr[i]        = __float2half_rn(cs * x1 - sn * x2);
    ptr[i + HALF] = __float2half_rn(sn * x1 + cs * x2);
}

// ---------------------------------------------------------------------------
// Row softmax over last dim (S=2048). Writes fp32 (output) and fp16 copy.
// ---------------------------------------------------------------------------
__global__ void softmax_kernel(float* __restrict__ attn, __half* __restrict__ p16)
{
    long row = blockIdx.x;                     // B*H*S rows
    float* p = attn + row * (long)SS;
    __half* ph = p16 + row * (long)SS;
    int t = threadIdx.x;
    float v[8];
    #pragma unroll
    for (int i = 0; i < 8; i++) v[i] = p[t + i * 256];

    float m = -3.4e38f;
    #pragma unroll
    for (int i = 0; i < 8; i++) m = fmaxf(m, v[i]);
    #pragma unroll
    for (int o = 16; o > 0; o >>= 1) m = fmaxf(m, __shfl_xor_sync(0xffffffffu, m, o));
    __shared__ float smax[8];
    __shared__ float ssum[8];
    if ((t & 31) == 0) smax[t >> 5] = m;
    __syncthreads();
    float bm = smax[0];
    #pragma unroll
    for (int i = 1; i < 8; i++) bm = fmaxf(bm, smax[i]);

    float sum = 0.f;
    #pragma unroll
    for (int i = 0; i < 8; i++) { v[i] = expf(v[i] - bm); sum += v[i]; }
    #pragma unroll
    for (int o = 16; o > 0; o >>= 1) sum += __shfl_xor_sync(0xffffffffu, sum, o);
    if ((t & 31) == 0) ssum[t >> 5] = sum;
    __syncthreads();
    float tot = 0.f;
    #pragma unroll
    for (int i = 0; i < 8; i++) tot += ssum[i];
    float invs = 1.0f / tot;
    #pragma unroll
    for (int i = 0; i < 8; i++) {
        float o = v[i] * invs;
        p[t + i * 256]  = o;
        ph[t + i * 256] = __float2half_rn(o);
    }
}

// ---------------------------------------------------------------------------
extern "C" void kernel_launch(void* const* d_in, const int* in_sizes, int n_in,
                              void* d_out, int out_size)
{
    const float* hs   = (const float*)d_in[0];
    const float* mask = (const float*)d_in[1];
    const int*   pos  = (const int*)  d_in[2];
    const float* Wq   = (const float*)d_in[3];
    const float* bq   = (const float*)d_in[4];
    const float* Wk   = (const float*)d_in[5];
    const float* bk   = (const float*)d_in[6];
    const float* Wv   = (const float*)d_in[7];
    const float* bv   = (const float*)d_in[8];
    const float* Wo   = (const float*)d_in[9];
    const float* bo   = (const float*)d_in[10];

    float* out  = (float*)d_out;                               // (B,S,HID)
    float* attn = out + (size_t)BB * SS * HIDD;                // (B,H,S,S)

    __half *hs16, *wq16, *wk16, *wv16, *wo16, *q16, *k16, *vt16, *p16, *oh16;
    cudaGetSymbolAddress((void**)&hs16, g_hs16);
    cudaGetSymbolAddress((void**)&wq16, g_wq16);
    cudaGetSymbolAddress((void**)&wk16, g_wk16);
    cudaGetSymbolAddress((void**)&wv16, g_wv16);
    cudaGetSymbolAddress((void**)&wo16, g_wo16);
    cudaGetSymbolAddress((void**)&q16,  g_q16);
    cudaGetSymbolAddress((void**)&k16,  g_k16);
    cudaGetSymbolAddress((void**)&vt16, g_vt16);
    cudaGetSymbolAddress((void**)&p16,  g_p16);
    cudaGetSymbolAddress((void**)&oh16, g_oh16);

    dim3 blk(256);
    const int M = BB * SS;          // 4096

    // convert inputs to fp16
    f2h_kernel<<<(BB * SS * HIDD) / 1024, 256>>>(hs, hs16, BB * SS * HIDD);
    f2h_kernel<<<(HIDD * HIDD) / 1024, 256>>>(Wq, wq16, HIDD * HIDD);
    f2h_kernel<<<(DD * HIDD) / 1024, 256>>>(Wk, wk16, DD * HIDD);
    f2h_kernel<<<(DD * HIDD) / 1024, 256>>>(Wv, wv16, DD * HIDD);
    f2h_kernel<<<(HIDD * HIDD) / 1024, 256>>>(Wo, wo16, HIDD * HIDD);

    // Q = hs @ Wq^T + bq  -> q16
    h_gemm<__half, 1><<<dim3(HIDD / 128, M / 128, 1), blk>>>(
        hs16, wq16, bq, q16, HIDD, HIDD, HIDD, HIDD, 1.0f,
        1, 0, 0, 0, 0, 0, 0, 0);
    // K = hs @ Wk^T + bk  -> k16
    h_gemm<__half, 1><<<dim3(DD / 128, M / 128, 1), blk>>>(
        hs16, wk16, bk, k16, HIDD, HIDD, HIDD, DD, 1.0f,
        1, 0, 0, 0, 0, 0, 0, 0);
    // vT[b] = Wv @ hs[b]^T + bv (row bias)  -> vt16 (b, d, s)
    h_gemm<__half, 2><<<dim3(SS / 128, DD / 128, BB), blk>>>(
        wv16, hs16, bv, vt16, HIDD, HIDD, HIDD, SS, 1.0f,
        1,
        0, 0,
        (long)SS * HIDD, 0,
        (long)DD * SS, 0,
        0);

    // RoPE on q16, k16
    rope_kernel<<<BB * SS * HH + BB * SS, 128>>>(q16, k16, pos);

    // scores = (q @ k^T) * D^-0.5 + mask -> attn (fp32, output)
    h_gemm<float, 1><<<dim3(SS / 128, SS / 128, BB * HH), blk>>>(
        q16, k16, mask, attn, DD, HIDD, DD, SS, 0.0625f,
        HH,
        (long)SS * HIDD, (long)DD,
        (long)SS * DD,   0,
        (long)HH * SS * SS, (long)SS * SS,
        (long)SS);

    // softmax -> attn (fp32) + p16 (fp16)
    softmax_kernel<<<BB * HH * SS, 256>>>(attn, p16);

    // oh = P @ vT^T  -> oh16 (b, s, h*D)
    h_gemm<__half, 0><<<dim3(DD / 128, SS / 128, BB * HH), blk>>>(
        p16, vt16, nullptr, oh16, SS, SS, SS, HIDD, 1.0f,
        HH,
        (long)HH * SS * SS, (long)SS * SS,
        (long)DD * SS, 0,
        (long)SS * HIDD, (long)DD,
        0);

    // out = oh @ Wo^T + bo  -> fp32 out
    h_gemm<float, 1><<<dim3(HIDD / 128, M / 128, 1), blk>>>(
        oh16, wo16, bo, out, HIDD, HIDD, HIDD, HIDD, 1.0f,
        1, 0, 0, 0, 0, 0, 0, 0);
}

// round 8
// speedup vs baseline: 5.5838x; 1.0553x over previous
#include <cuda_runtime.h>
#include <cuda_fp16.h>
#include <math.h>
#include <stdint.h>

// Problem constants
#define BB   2
#define SS   2048
#define HIDD 2048
#define HH   8
#define DD   256
#define HALF 128
#define NQK  2304   // 2048 + 256 (fused Q,K projection)

// fp16 scratch (device globals; no allocation allowed)
__device__ __half g_hs16 [BB * SS * HIDD];
__device__ __half g_wqk16[NQK * HIDD];        // [Wq; Wk] stacked rows
__device__ __half g_wv16 [DD * HIDD];
__device__ __half g_wo16 [HIDD * HIDD];
__device__ float  g_bqk  [NQK];
__device__ __half g_q16 [BB * SS * HH * DD];  // (b,s,h,d) flat (4096, 2048)
__device__ __half g_k16 [BB * SS * DD];       // flat (4096, 256)
__device__ __half g_vt16[BB * DD * SS];       // (b,d,s) = V^T
__device__ __half g_p16 [(size_t)BB * HH * SS * SS];
__device__ __half g_oh16[BB * SS * HH * DD];  // flat (4096, 2048)

// ---------------------------------------------------------------------------
__device__ __forceinline__ uint32_t smem_u32(const void* p) {
    uint32_t a;
    asm("{ .reg .u64 t; cvta.to.shared.u64 t, %1; cvt.u32.u64 %0, t; }" : "=r"(a) : "l"(p));
    return a;
}
__device__ __forceinline__ void cpa16(uint32_t dst, const void* src) {
    asm volatile("cp.async.cg.shared.global [%0], [%1], 16;" :: "r"(dst), "l"(src) : "memory");
}
#define CP_COMMIT() asm volatile("cp.async.commit_group;" ::: "memory")

__device__ __forceinline__ void ldsm4(uint32_t r[4], uint32_t addr) {
    asm volatile("ldmatrix.sync.aligned.m8n8.x4.shared.b16 {%0,%1,%2,%3}, [%4];"
                 : "=r"(r[0]), "=r"(r[1]), "=r"(r[2]), "=r"(r[3]) : "r"(addr));
}
__device__ __forceinline__ void mma_f16(float c[4], const uint32_t a[4], const uint32_t* b) {
    asm volatile(
        "mma.sync.aligned.m16n8k16.row.col.f32.f16.f16.f32 "
        "{%0,%1,%2,%3}, {%4,%5,%6,%7}, {%8,%9}, {%0,%1,%2,%3};"
        : "+f"(c[0]), "+f"(c[1]), "+f"(c[2]), "+f"(c[3])
        : "r"(a[0]), "r"(a[1]), "r"(a[2]), "r"(a[3]), "r"(b[0]), "r"(b[1]));
}

// ---------------------------------------------------------------------------
// fp16 NT GEMM: C = alpha * A(M,K) @ B(N,K)^T + bias   (both operands k-contig)
//   MODE: 0 none, 1 column bias Add[n] (fp32), 2 row bias Add[m],
//         3 fused Q|K routing (cols <2048 -> C as q, else -> Ck)
// Block 128x128x32, 256 threads (8 warps, 2x4), warp tile 64x32.
// Double-buffered smem via cp.async; ldmatrix fragment loads.
// Requires M,N % 128 == 0, K % 32 == 0.  (identical mainloop to round-5 kernel)
// ---------------------------------------------------------------------------
#define APITCH 80   // bytes per 32-half row (64B data + 16B pad)

template <typename CT, int MODE>
__global__ void __launch_bounds__(256, 2)
h_gemm(const __half* __restrict__ A, const __half* __restrict__ B,
       const float* __restrict__ Add, CT* __restrict__ C, __half* __restrict__ Ck,
       int K, int lda, int ldb, int ldc, float alpha, int Hz,
       long aSB, long aSH, long bSB, long bSH, long cSB, long cSH, long addSB)
{
    __shared__ __align__(16) char smem[4 * 128 * APITCH + 512];
    const uint32_t sb = smem_u32(smem);
    const uint32_t AsS[2] = {sb,                  sb + 128 * APITCH};
    const uint32_t BsS[2] = {sb + 2*128*APITCH,   sb + 3*128*APITCH};
    float* add_s = (float*)(smem + 4 * 128 * APITCH);

    const int tid  = threadIdx.x;
    const int warp = tid >> 5, lane = tid & 31;
    const int gid  = lane >> 2, tid4 = lane & 3;
    const int wm0  = (warp >> 2) * 64;
    const int wn0  = (warp & 3) * 32;

    const int z  = blockIdx.z;
    const int zb = z / Hz;
    const int zh = z - zb * Hz;
    A += zb * aSB + zh * aSH;
    B += zb * bSB + zh * bSH;
    C += zb * cSB + zh * cSH;

    const int n0c = blockIdx.x * 128;
    if (MODE == 1 && tid < 128) add_s[tid] = Add[zb * addSB + n0c + tid];
    if (MODE == 3 && tid < 128) add_s[tid] = Add[n0c + tid];

    const __half* Ab = A + (long)(blockIdx.y * 128) * lda;
    const __half* Bb = B + (long)n0c * ldb;

    // cp.async mapping: 2 threads per row, 2x16B each
    const int lrow = tid >> 1;
    const int lch  = (tid & 1) * 16;   // halves offset (0 or 16)

    const int nIt = K / 32;

    // fragment smem addresses
    const uint32_t aoff = (uint32_t)((wm0 + (lane & 15)) * APITCH + (lane >> 4) * 16);
    const uint32_t boff = (uint32_t)((wn0 + (lane & 7) + ((lane >> 4) & 1) * 8) * APITCH
                                     + ((lane >> 3) & 1) * 16);

    float c[4][4][4];
    #pragma unroll
    for (int im = 0; im < 4; im++)
        #pragma unroll
        for (int in = 0; in < 4; in++)
            #pragma unroll
            for (int r = 0; r < 4; r++) c[im][in][r] = 0.f;

    // prologue: fetch tiles 0, 1
    #pragma unroll
    for (int p = 0; p < 2; p++) {
        const int k0 = p * 32;
        const uint32_t da = AsS[p] + lrow * APITCH + lch * 2;
        const uint32_t db = BsS[p] + lrow * APITCH + lch * 2;
        cpa16(da,      Ab + (long)lrow * lda + k0 + lch);
        cpa16(da + 16, Ab + (long)lrow * lda + k0 + lch + 8);
        cpa16(db,      Bb + (long)lrow * ldb + k0 + lch);
        cpa16(db + 16, Bb + (long)lrow * ldb + k0 + lch + 8);
        CP_COMMIT();
    }

    for (int it = 0; it < nIt; ++it) {
        const int buf = it & 1;
        if (it + 1 < nIt) asm volatile("cp.async.wait_group 1;" ::: "memory");
        else              asm volatile("cp.async.wait_group 0;" ::: "memory");
        __syncthreads();

        // compute on buf
        #pragma unroll
        for (int kk = 0; kk < 32; kk += 16) {
            uint32_t af[4][4], bf[2][4];
            #pragma unroll
            for (int im = 0; im < 4; im++)
                ldsm4(af[im], AsS[buf] + aoff + im * (16 * APITCH) + kk * 2);
            #pragma unroll
            for (int ng = 0; ng < 2; ng++)
                ldsm4(bf[ng], BsS[buf] + boff + ng * (16 * APITCH) + kk * 2);
            #pragma unroll
            for (int im = 0; im < 4; im++)
                #pragma unroll
                for (int in = 0; in < 4; in++)
                    mma_f16(c[im][in], af[im], &bf[in >> 1][(in & 1) * 2]);
        }
        __syncthreads();

        // fetch tile it+2 into buf
        if (it + 2 < nIt) {
            const int k0 = (it + 2) * 32;
            const uint32_t da = AsS[buf] + lrow * APITCH + lch * 2;
            const uint32_t db = BsS[buf] + lrow * APITCH + lch * 2;
            cpa16(da,      Ab + (long)lrow * lda + k0 + lch);
            cpa16(da + 16, Ab + (long)lrow * lda + k0 + lch + 8);
            cpa16(db,      Bb + (long)lrow * ldb + k0 + lch);
            cpa16(db + 16, Bb + (long)lrow * ldb + k0 + lch + 8);
            CP_COMMIT();
        }
    }

    // ---- epilogue ----
    const int m0 = blockIdx.y * 128 + wm0;

    // MODE 3: route to q (cols < 2048) or k (cols >= 2048); boundaries 128-aligned
    __half* Cp16 = nullptr; int ldc3 = 0; int nbase3 = 0;
    if (MODE == 3) {
        if (n0c < 2048) { Cp16 = (__half*)C; ldc3 = 2048; nbase3 = n0c; }
        else            { Cp16 = Ck;         ldc3 = 256;  nbase3 = n0c - 2048; }
    }

    float rb0 = 0.f, rb1 = 0.f;
    #pragma unroll
    for (int im = 0; im < 4; im++) {
        const long r0 = m0 + im * 16 + gid;
        if (MODE == 2) {
            rb0 = Add[zb * addSB + r0];
            rb1 = Add[zb * addSB + r0 + 8];
        }
        #pragma unroll
        for (int in = 0; in < 4; in++) {
            const int lc = wn0 + in * 8 + tid4 * 2;     // local col in [0,128)
            float b0 = 0.f, b1 = 0.f;
            if (MODE == 1 || MODE == 3) { b0 = add_s[lc]; b1 = add_s[lc + 1]; }
            float v0 = c[im][in][0] * alpha + (MODE == 2 ? rb0 : b0);
            float v1 = c[im][in][1] * alpha + (MODE == 2 ? rb0 : b1);
            float v2 = c[im][in][2] * alpha + (MODE == 2 ? rb1 : b0);
            float v3 = c[im][in][3] * alpha + (MODE == 2 ? rb1 : b1);
            if (MODE == 3) {
                *(__half2*)&Cp16[r0 * ldc3 + nbase3 + lc]       = __floats2half2_rn(v0, v1);
                *(__half2*)&Cp16[(r0 + 8) * ldc3 + nbase3 + lc] = __floats2half2_rn(v2, v3);
            } else if (sizeof(CT) == 4) {
                float* Cp = (float*)C;
                *(float2*)&Cp[r0 * ldc + n0c + lc]       = make_float2(v0, v1);
                *(float2*)&Cp[(r0 + 8) * ldc + n0c + lc] = make_float2(v2, v3);
            } else {
                __half* Cp = (__half*)C;
                *(__half2*)&Cp[r0 * ldc + n0c + lc]       = __floats2half2_rn(v0, v1);
                *(__half2*)&Cp[(r0 + 8) * ldc + n0c + lc] = __floats2half2_rn(v2, v3);
            }
        }
    }
}

// ---------------------------------------------------------------------------
// fp32 -> fp16 convert (n % 1024 == 0)
// ---------------------------------------------------------------------------
__global__ void f2h_kernel(const float* __restrict__ src, __half* __restrict__ dst, int n)
{
    int i = (blockIdx.x * 256 + threadIdx.x) * 4;
    if (i < n) {
        float4 v = *(const float4*)(src + i);
        *(__half2*)(dst + i)     = __floats2half2_rn(v.x, v.y);
        *(__half2*)(dst + i + 2) = __floats2half2_rn(v.z, v.w);
    }
}

// bias concat [bq(2048); bk(256)] -> g_bqk
__global__ void bias_concat(const float* __restrict__ bq, const float* __restrict__ bk,
                            float* __restrict__ dst)
{
    int i = blockIdx.x * 256 + threadIdx.x;
    if (i < 2048)     dst[i] = bq[i];
    else if (i < NQK) dst[i] = bk[i - 2048];
}

// ---------------------------------------------------------------------------
// RoPE in fp16: in-place on g_q16 (B*S*H rows) and g_k16 (B*S rows).
// ---------------------------------------------------------------------------
__global__ void rope_kernel(__half* __restrict__ q, __half* __restrict__ k,
                            const int* __restrict__ pos)
{
    int bid = blockIdx.x;
    const int NQ = BB * SS * HH;
    __half* ptr;
    int b, s;
    if (bid < NQ) {
        int h = bid % HH;
        s = (bid / HH) % SS;
        b = bid / (HH * SS);
        ptr = q + (((long)(b * SS + s)) * HH + h) * DD;
    } else {
        int idx = bid - NQ;
        s = idx % SS;
        b = idx / SS;
        ptr = k + ((long)(b * SS + s)) * DD;
    }
    int i = threadIdx.x;                       // 0..127
    float p = (float)pos[b * SS + s];
    float inv = powf(10000.0f, -((float)(2 * i)) / (float)DD);
    float fr = p * inv;
    float cs, sn;
    sincosf(fr, &sn, &cs);
    float x1 = __half2float(ptr[i]);
    float x2 = __half2float(ptr[i + HALF]);
    ptr[i]        = __float2half_rn(cs * x1 - sn * x2);
    ptr[i + HALF] = __float2half_rn(sn * x1 + cs * x2);
}

// ---------------------------------------------------------------------------
// Row softmax over last dim (S=2048). Writes fp32 (output) and fp16 copy.
// ---------------------------------------------------------------------------
__global__ void softmax_kernel(float* __restrict__ attn, __half* __restrict__ p16)
{
    long row = blockIdx.x;
    float* p = attn + row * (long)SS;
    __half* ph = p16 + row * (long)SS;
    int t = threadIdx.x;
    float v[8];
    #pragma unroll
    for (int i = 0; i < 8; i++) v[i] = p[t + i * 256];

    float m = -3.4e38f;
    #pragma unroll
    for (int i = 0; i < 8; i++) m = fmaxf(m, v[i]);
    #pragma unroll
    for (int o = 16; o > 0; o >>= 1) m = fmaxf(m, __shfl_xor_sync(0xffffffffu, m, o));
    __shared__ float smax[8];
    __shared__ float ssum[8];
    if ((t & 31) == 0) smax[t >> 5] = m;
    __syncthreads();
    float bm = smax[0];
    #pragma unroll
    for (int i = 1; i < 8; i++) bm = fmaxf(bm, smax[i]);

    float sum = 0.f;
    #pragma unroll
    for (int i = 0; i < 8; i++) { v[i] = __expf(v[i] - bm); sum += v[i]; }
    #pragma unroll
    for (int o = 16; o > 0; o >>= 1) sum += __shfl_xor_sync(0xffffffffu, sum, o);
    if ((t & 31) == 0) ssum[t >> 5] = sum;
    __syncthreads();
    float tot = 0.f;
    #pragma unroll
    for (int i = 0; i < 8; i++) tot += ssum[i];
    float invs = 1.0f / tot;
    #pragma unroll
    for (int i = 0; i < 8; i++) {
        float o = v[i] * invs;
        p[t + i * 256]  = o;
        ph[t + i * 256] = __float2half_rn(o);
    }
}

// ---------------------------------------------------------------------------
extern "C" void kernel_launch(void* const* d_in, const int* in_sizes, int n_in,
                              void* d_out, int out_size)
{
    const float* hs   = (const float*)d_in[0];
    const float* mask = (const float*)d_in[1];
    const int*   pos  = (const int*)  d_in[2];
    const float* Wq   = (const float*)d_in[3];
    const float* bq   = (const float*)d_in[4];
    const float* Wk   = (const float*)d_in[5];
    const float* bk   = (const float*)d_in[6];
    const float* Wv   = (const float*)d_in[7];
    const float* bv   = (const float*)d_in[8];
    const float* Wo   = (const float*)d_in[9];
    const float* bo   = (const float*)d_in[10];

    float* out  = (float*)d_out;                               // (B,S,HID)
    float* attn = out + (size_t)BB * SS * HIDD;                // (B,H,S,S)

    __half *hs16, *wqk16, *wv16, *wo16, *q16, *k16, *vt16, *p16, *oh16;
    float* bqk;
    cudaGetSymbolAddress((void**)&hs16,  g_hs16);
    cudaGetSymbolAddress((void**)&wqk16, g_wqk16);
    cudaGetSymbolAddress((void**)&wv16,  g_wv16);
    cudaGetSymbolAddress((void**)&wo16,  g_wo16);
    cudaGetSymbolAddress((void**)&bqk,   g_bqk);
    cudaGetSymbolAddress((void**)&q16,   g_q16);
    cudaGetSymbolAddress((void**)&k16,   g_k16);
    cudaGetSymbolAddress((void**)&vt16,  g_vt16);
    cudaGetSymbolAddress((void**)&p16,   g_p16);
    cudaGetSymbolAddress((void**)&oh16,  g_oh16);

    dim3 blk(256);
    const int M = BB * SS;          // 4096

    // fp16 conversions (Wq, Wk stacked into one buffer)
    f2h_kernel<<<(BB * SS * HIDD) / 1024, 256>>>(hs, hs16, BB * SS * HIDD);
    f2h_kernel<<<(HIDD * HIDD) / 1024, 256>>>(Wq, wqk16, HIDD * HIDD);
    f2h_kernel<<<(DD * HIDD) / 1024, 256>>>(Wk, wqk16 + (size_t)2048 * HIDD, DD * HIDD);
    f2h_kernel<<<(DD * HIDD) / 1024, 256>>>(Wv, wv16, DD * HIDD);
    f2h_kernel<<<(HIDD * HIDD) / 1024, 256>>>(Wo, wo16, HIDD * HIDD);
    bias_concat<<<NQK / 256, 256>>>(bq, bk, bqk);

    // fused Q|K projection: (4096 x 2304) = hs @ [Wq;Wk]^T + bqk -> q16, k16
    h_gemm<__half, 3><<<dim3(NQK / 128, M / 128, 1), blk>>>(
        hs16, wqk16, bqk, q16, k16,
        HIDD, HIDD, HIDD, 0, 1.0f, 1, 0, 0, 0, 0, 0, 0, 0);

    // vT[b] = Wv @ hs[b]^T + bv (row bias) -> vt16 (b, d, s)
    h_gemm<__half, 2><<<dim3(SS / 128, DD / 128, BB), blk>>>(
        wv16, hs16, bv, vt16, nullptr,
        HIDD, HIDD, HIDD, SS, 1.0f, 1,
        0, 0,
        (long)SS * HIDD, 0,
        (long)DD * SS, 0,
        0);

    // RoPE on q16, k16
    rope_kernel<<<BB * SS * HH + BB * SS, 128>>>(q16, k16, pos);

    // scores = (q @ k^T) * D^-0.5 + mask -> attn (fp32, output)
    h_gemm<float, 1><<<dim3(SS / 128, SS / 128, BB * HH), blk>>>(
        q16, k16, mask, attn, nullptr,
        DD, HIDD, DD, SS, 0.0625f, HH,
        (long)SS * HIDD, (long)DD,
        (long)SS * DD,   0,
        (long)HH * SS * SS, (long)SS * SS,
        (long)SS);

    // softmax -> attn (fp32) + p16 (fp16)
    softmax_kernel<<<BB * HH * SS, 256>>>(attn, p16);

    // oh = P @ vT^T (NT with B = vT) -> oh16 (b, s, h*D)
    h_gemm<__half, 0><<<dim3(DD / 128, SS / 128, BB * HH), blk>>>(
        p16, vt16, nullptr, oh16, nullptr,
        SS, SS, SS, HIDD, 1.0f, HH,
        (long)HH * SS * SS, (long)SS * SS,
        (long)DD * SS, 0,
        (long)SS * HIDD, (long)DD,
        0);

    // out = oh @ Wo^T + bo -> fp32
    h_gemm<float, 1><<<dim3(HIDD / 128, M / 128, 1), blk>>>(
        oh16, wo16, bo, out, nullptr,
        HIDD, HIDD, HIDD, HIDD, 1.0f, 1, 0, 0, 0, 0, 0, 0, 0);
}